// round 1
// baseline (speedup 1.0000x reference)
#include <cuda_runtime.h>
#include <cuda_bf16.h>
#include <mma.h>
#include <math.h>

using namespace nvcuda;

// ---------------- problem constants ----------------
#define PB 32          // batch
#define SS 512         // seq
#define DD 768
#define HH 12
#define EE 64
#define LL 12
#define PP 20          // prefix len
#define NEXP 9
#define NT (PB*SS)     // 16384 tokens
#define KV_RAW (PP+SS)        // 532
#define KV_PAD 576            // padded keys (multiple of 64)
#define QKV_COLS (3*DD)       // 2304
#define FFN_COLS (4*DD)       // 3072

// ---------------- scratch (device globals; no runtime alloc) ----------------
__device__ float g_x   [(long long)NT*DD];
__device__ float g_tmp [(long long)NT*DD];
__device__ float g_ctx [(long long)NT*DD];
__device__ float g_qkv [(long long)NT*QKV_COLS];
__device__ float g_hdn [(long long)NT*FFN_COLS];
__device__ float g_kf  [(long long)PB*HH*KV_PAD*EE];
__device__ float g_vf  [(long long)PB*HH*KV_PAD*EE];
__device__ float g_scores[(long long)PB*HH*SS*KV_PAD];   // 113.2M floats
__device__ float g_ck  [PP*DD];
__device__ float g_cv  [PP*DD];
__device__ float g_cvp [PP*DD];
__device__ float g_gl  [NEXP];
__device__ float g_w   [NEXP];
__device__ float g_moe [1];
__device__ float g_pooled[PB*DD];

// ---------------- reductions ----------------
__device__ __forceinline__ float block_reduce_sum(float v, float* red) {
    int lane = threadIdx.x & 31, wid = threadIdx.x >> 5;
    #pragma unroll
    for (int o = 16; o > 0; o >>= 1) v += __shfl_down_sync(0xffffffffu, v, o);
    if (lane == 0) red[wid] = v;
    __syncthreads();
    int nw = (blockDim.x + 31) >> 5;
    v = (threadIdx.x < nw) ? red[threadIdx.x] : 0.f;
    if (wid == 0) {
        #pragma unroll
        for (int o = 16; o > 0; o >>= 1) v += __shfl_down_sync(0xffffffffu, v, o);
        if (lane == 0) red[0] = v;
    }
    __syncthreads();
    float r = red[0];
    __syncthreads();
    return r;
}

__device__ __forceinline__ float block_reduce_max(float v, float* red) {
    int lane = threadIdx.x & 31, wid = threadIdx.x >> 5;
    #pragma unroll
    for (int o = 16; o > 0; o >>= 1) v = fmaxf(v, __shfl_down_sync(0xffffffffu, v, o));
    if (lane == 0) red[wid] = v;
    __syncthreads();
    int nw = (blockDim.x + 31) >> 5;
    v = (threadIdx.x < nw) ? red[threadIdx.x] : -1e30f;
    if (wid == 0) {
        #pragma unroll
        for (int o = 16; o > 0; o >>= 1) v = fmaxf(v, __shfl_down_sync(0xffffffffu, v, o));
        if (lane == 0) red[0] = v;
    }
    __syncthreads();
    float r = red[0];
    __syncthreads();
    return r;
}

// ---------------- tf32 WMMA GEMM: C = A * B (or A * B^T) ----------------
// BM=128, BN=64, BK=16; 256 threads, 8 warps (4 along M, 2 along N), warp tile 32x32.
// All M,N,K are exact multiples of the tile dims by construction.
#define BM 128
#define BN 64
#define BK 16

template<bool BT>
__global__ void gemm_tf32_kernel(const float* __restrict__ A, const float* __restrict__ B,
                                 float* __restrict__ C,
                                 int M, int N, int K, int lda, int ldb, int ldc,
                                 int inner,
                                 long long isA, long long osA,
                                 long long isB, long long osB,
                                 long long isC, long long osC)
{
    __shared__ float As[BM][BK + 8];   // ld = 24 (mult of 8)
    __shared__ float Bs[BK][BN + 8];   // ld = 72 (mult of 8)

    int z = blockIdx.z;
    long long zi = z % inner, zo = z / inner;
    const float* Ab = A + zi * isA + zo * osA;
    const float* Bb = B + zi * isB + zo * osB;
    float*       Cb = C + zi * isC + zo * osC;

    int bm = blockIdx.y * BM;
    int bn = blockIdx.x * BN;
    int tid = threadIdx.x;
    int warp = tid >> 5;
    int wm = warp & 3;
    int wn = warp >> 2;

    wmma::fragment<wmma::accumulator, 16, 16, 8, float> acc[2][2];
    #pragma unroll
    for (int i = 0; i < 2; i++)
        #pragma unroll
        for (int j = 0; j < 2; j++) wmma::fill_fragment(acc[i][j], 0.f);

    for (int k0 = 0; k0 < K; k0 += BK) {
        #pragma unroll 4
        for (int t = tid; t < BM * BK; t += 256) {
            int r = t >> 4, c = t & 15;
            As[r][c] = Ab[(long long)(bm + r) * lda + k0 + c];
        }
        #pragma unroll 2
        for (int t = tid; t < BK * BN; t += 256) {
            int r = t >> 6, c = t & 63;
            float v;
            if (BT) v = Bb[(long long)(bn + c) * ldb + k0 + r];
            else    v = Bb[(long long)(k0 + r) * ldb + bn + c];
            Bs[r][c] = v;
        }
        __syncthreads();
        #pragma unroll
        for (int kk = 0; kk < BK; kk += 8) {
            wmma::fragment<wmma::matrix_a, 16, 16, 8, wmma::precision::tf32, wmma::row_major> af[2];
            wmma::fragment<wmma::matrix_b, 16, 16, 8, wmma::precision::tf32, wmma::row_major> bf[2];
            #pragma unroll
            for (int i = 0; i < 2; i++) {
                wmma::load_matrix_sync(af[i], &As[wm * 32 + i * 16][kk], BK + 8);
                #pragma unroll
                for (int t = 0; t < af[i].num_elements; t++)
                    af[i].x[t] = wmma::__float_to_tf32(af[i].x[t]);
            }
            #pragma unroll
            for (int j = 0; j < 2; j++) {
                wmma::load_matrix_sync(bf[j], &Bs[kk][wn * 32 + j * 16], BN + 8);
                #pragma unroll
                for (int t = 0; t < bf[j].num_elements; t++)
                    bf[j].x[t] = wmma::__float_to_tf32(bf[j].x[t]);
            }
            #pragma unroll
            for (int i = 0; i < 2; i++)
                #pragma unroll
                for (int j = 0; j < 2; j++)
                    wmma::mma_sync(acc[i][j], af[i], bf[j], acc[i][j]);
        }
        __syncthreads();
    }
    #pragma unroll
    for (int i = 0; i < 2; i++)
        #pragma unroll
        for (int j = 0; j < 2; j++)
            wmma::store_matrix_sync(
                &Cb[(long long)(bm + wm * 32 + i * 16) * ldc + bn + wn * 32 + j * 16],
                acc[i][j], ldc, wmma::mem_row_major);
}

static void gemm(const float* A, const float* B, float* C,
                 int M, int N, int K, int lda, int ldb, int ldc, bool bt,
                 int batch = 1, int inner = 1,
                 long long isA = 0, long long osA = 0,
                 long long isB = 0, long long osB = 0,
                 long long isC = 0, long long osC = 0)
{
    dim3 g(N / BN, M / BM, batch), blk(256);
    if (bt) gemm_tf32_kernel<true ><<<g, blk>>>(A, B, C, M, N, K, lda, ldb, ldc, inner, isA, osA, isB, osB, isC, osC);
    else    gemm_tf32_kernel<false><<<g, blk>>>(A, B, C, M, N, K, lda, ldb, ldc, inner, isA, osA, isB, osB, isC, osC);
}

// ---------------- misc kernels ----------------
__global__ void init_kernel() { g_moe[0] = 0.f; }

__global__ void embed_ln_kernel(const int* __restrict__ ids,
                                const float* __restrict__ we,
                                const float* __restrict__ pe,
                                const float* __restrict__ te,
                                const float* __restrict__ g,
                                const float* __restrict__ b)
{
    int t = blockIdx.x;
    int s = t & (SS - 1);
    int id = ids[t];
    __shared__ float buf[DD];
    __shared__ float red[32];
    for (int d = threadIdx.x; d < DD; d += blockDim.x)
        buf[d] = we[(long long)id * DD + d] + pe[(long long)s * DD + d] + te[d];
    __syncthreads();
    float s0 = 0.f;
    for (int d = threadIdx.x; d < DD; d += blockDim.x) s0 += buf[d];
    float mean = block_reduce_sum(s0, red) * (1.f / DD);
    float v0 = 0.f;
    for (int d = threadIdx.x; d < DD; d += blockDim.x) { float df = buf[d] - mean; v0 += df * df; }
    float var = block_reduce_sum(v0, red) * (1.f / DD);
    float inv = rsqrtf(var + 1e-12f);
    for (int d = threadIdx.x; d < DD; d += blockDim.x)
        g_x[(long long)t * DD + d] = (buf[d] - mean) * inv * g[d] + b[d];
}

// x = LN(x + delta + bias)
__global__ void add_ln_kernel(float* __restrict__ x, const float* __restrict__ delta,
                              const float* __restrict__ bias,
                              const float* __restrict__ g, const float* __restrict__ b)
{
    int t = blockIdx.x;
    __shared__ float buf[DD];
    __shared__ float red[32];
    for (int d = threadIdx.x; d < DD; d += blockDim.x)
        buf[d] = x[(long long)t * DD + d] + delta[(long long)t * DD + d] + bias[d];
    __syncthreads();
    float s0 = 0.f;
    for (int d = threadIdx.x; d < DD; d += blockDim.x) s0 += buf[d];
    float mean = block_reduce_sum(s0, red) * (1.f / DD);
    float v0 = 0.f;
    for (int d = threadIdx.x; d < DD; d += blockDim.x) { float df = buf[d] - mean; v0 += df * df; }
    float var = block_reduce_sum(v0, red) * (1.f / DD);
    float inv = rsqrtf(var + 1e-12f);
    for (int d = threadIdx.x; d < DD; d += blockDim.x)
        x[(long long)t * DD + d] = (buf[d] - mean) * inv * g[d] + b[d];
}

__global__ void bias_add_kernel(float* __restrict__ buf, const float* __restrict__ bias,
                                long long total, int cols)
{
    long long i = (long long)blockIdx.x * blockDim.x + threadIdx.x;
    if (i >= total) return;
    int c = (int)(i % cols);
    buf[i] += bias[c];
}

__global__ void bias_gelu_kernel(float* __restrict__ buf, const float* __restrict__ bias,
                                 long long total, int cols)
{
    long long i = (long long)blockIdx.x * blockDim.x + threadIdx.x;
    if (i >= total) return;
    int c = (int)(i % cols);
    float v = buf[i] + bias[c];
    buf[i] = 0.5f * v * (1.f + erff(v * 0.70710678118654752f));
}

// gate logits: one block per expert n
__global__ void gate_logits_kernel(const float* __restrict__ emb,
                                   const float* __restrict__ gw,
                                   const float* __restrict__ gb, int l)
{
    int n = blockIdx.x;
    __shared__ float red[32];
    float acc = 0.f;
    for (int i = threadIdx.x; i < PP * DD; i += blockDim.x) {
        int p = i / DD, rest = i - p * DD;
        long long off = (long long)p * (LL * 2 * DD) + (long long)l * (2 * DD) + rest;
        float gi = 0.f;
        #pragma unroll
        for (int e = 0; e < NEXP; e++)
            gi += emb[(long long)e * PP * LL * 2 * DD + off];
        acc += gi * gw[(long long)l * (PP * DD * NEXP) + (long long)i * NEXP + n];
    }
    acc = block_reduce_sum(acc, red);
    if (threadIdx.x == 0) g_gl[n] = acc + gb[l * NEXP + n];
}

__global__ void gate_finalize_kernel()
{
    if (threadIdx.x == 0) {
        float mx = g_gl[0];
        #pragma unroll
        for (int i = 1; i < NEXP; i++) mx = fmaxf(mx, g_gl[i]);
        float e[NEXP], s = 0.f;
        #pragma unroll
        for (int i = 0; i < NEXP; i++) { e[i] = expf(g_gl[i] - mx); s += e[i]; }
        float inv = 1.f / s, m2 = 0.f;
        #pragma unroll
        for (int i = 0; i < NEXP; i++) { float wi = e[i] * inv; g_w[i] = wi; m2 += wi * wi; }
        g_moe[0] += m2;
    }
}

__global__ void ckcv_kernel(const float* __restrict__ emb, int l)
{
    int i = blockIdx.x * blockDim.x + threadIdx.x;
    if (i >= PP * DD) return;
    int p = i / DD, rest = i - p * DD;
    long long off = (long long)p * (LL * 2 * DD) + (long long)l * (2 * DD) + rest;
    float sk = 0.f, sv = 0.f;
    #pragma unroll
    for (int e = 0; e < NEXP; e++) {
        long long eb = (long long)e * PP * LL * 2 * DD;
        float w = g_w[e];
        sk += w * emb[eb + off];
        sv += w * emb[eb + off + DD];
    }
    g_ck[i] = sk;
    g_cv[i] = sv;
}

__global__ void proj_cv_kernel(const float* __restrict__ pw, const float* __restrict__ pb, int l)
{
    int i = blockIdx.x * blockDim.x + threadIdx.x;
    if (i >= PP * DD) return;
    int p = i / DD, j = i - p * DD;
    const float* W = pw + (long long)l * DD * DD;
    float s = pb[l * DD + j];
    const float* cvr = g_cv + p * DD;
    for (int d = 0; d < DD; d++) s += cvr[d] * W[(long long)d * DD + j];
    g_cvp[i] = s;
}

__global__ void fill_kfvf_kernel()
{
    long long idx = (long long)blockIdx.x * blockDim.x + threadIdx.x;
    const long long total = (long long)PB * HH * KV_PAD * EE;
    if (idx >= total) return;
    int c = (int)(idx & (EE - 1));
    long long r = idx >> 6;
    int row = (int)(r % KV_PAD);
    long long bh = r / KV_PAD;
    int h = (int)(bh % HH);
    int b = (int)(bh / HH);
    float kvv, vvv;
    if (row < PP) {
        kvv = g_ck[row * DD + h * EE + c];
        vvv = g_cvp[row * DD + h * EE + c];
    } else if (row < KV_RAW) {
        int s = row - PP;
        long long base = ((long long)(b * SS + s)) * QKV_COLS + h * EE + c;
        kvv = g_qkv[base + DD];
        vvv = g_qkv[base + 2 * DD];
    } else {
        kvv = 0.f; vvv = 0.f;
    }
    g_kf[idx] = kvv;
    g_vf[idx] = vvv;
}

__global__ void attn_softmax_kernel(const float* __restrict__ amask)
{
    long long row = blockIdx.x;                 // over B*H*S
    int b = (int)(row / (HH * SS));
    float* srow = g_scores + row * KV_PAD;
    const float scale = 0.125f;                 // 1/sqrt(64)
    __shared__ float red[32];
    int tid = threadIdx.x;

    float mx = -1e30f;
    for (int j = tid; j < KV_RAW; j += blockDim.x) {
        float bias = 0.f;
        if (j >= PP) bias = (1.0f - amask[(long long)b * SS + (j - PP)]) * -10000.0f;
        float v = srow[j] * scale + bias;
        srow[j] = v;
        mx = fmaxf(mx, v);
    }
    mx = block_reduce_max(mx, red);
    float sum = 0.f;
    for (int j = tid; j < KV_RAW; j += blockDim.x) {
        float e = __expf(srow[j] - mx);
        srow[j] = e;
        sum += e;
    }
    sum = block_reduce_sum(sum, red);
    float inv = 1.f / sum;
    for (int j = tid; j < KV_RAW; j += blockDim.x) srow[j] *= inv;
    for (int j = KV_RAW + tid; j < KV_PAD; j += blockDim.x) srow[j] = 0.f;
}

__global__ void pool_kernel(const float* __restrict__ pw, const float* __restrict__ pb)
{
    int i = blockIdx.x * blockDim.x + threadIdx.x;
    if (i >= PB * DD) return;
    int b = i / DD, j = i - b * DD;
    float s = pb[j];
    const float* xr = g_x + (long long)b * SS * DD;   // token 0 of batch b
    for (int d = 0; d < DD; d++) s += xr[d] * pw[(long long)d * DD + j];
    g_pooled[i] = tanhf(s);
}

__global__ void final_kernel(const float* __restrict__ fw, const float* __restrict__ fb,
                             float* __restrict__ out, int out_size)
{
    int i = blockIdx.x * blockDim.x + threadIdx.x;
    if (i < PB * 2) {
        int b = i >> 1, c = i & 1;
        float s = fb[c];
        const float* pr = g_pooled + b * DD;
        for (int j = 0; j < DD; j++) s += pr[j] * fw[j * 2 + c];
        out[i] = s;
    }
    if (i == PB * 2 && out_size > PB * 2) out[PB * 2] = g_moe[0] / (float)LL;
}

// ---------------- launch ----------------
extern "C" void kernel_launch(void* const* d_in, const int* in_sizes, int n_in,
                              void* d_out, int out_size)
{
    const int*   input_ids  = (const int*)  d_in[0];
    const float* attn_mask  = (const float*)d_in[1];
    const float* expert_emb = (const float*)d_in[2];
    const float* gate_w     = (const float*)d_in[3];
    const float* gate_b     = (const float*)d_in[4];
    const float* proj_w     = (const float*)d_in[5];
    const float* proj_b     = (const float*)d_in[6];
    const float* word_emb   = (const float*)d_in[7];
    const float* pos_emb    = (const float*)d_in[8];
    const float* type_emb   = (const float*)d_in[9];
    const float* emb_ln_g   = (const float*)d_in[10];
    const float* emb_ln_b   = (const float*)d_in[11];
    const float* qkv_w      = (const float*)d_in[12];
    const float* qkv_b      = (const float*)d_in[13];
    const float* attn_out_w = (const float*)d_in[14];
    const float* attn_out_b = (const float*)d_in[15];
    const float* ln1_g      = (const float*)d_in[16];
    const float* ln1_b      = (const float*)d_in[17];
    const float* ffn1_w     = (const float*)d_in[18];
    const float* ffn1_b     = (const float*)d_in[19];
    const float* ffn2_w     = (const float*)d_in[20];
    const float* ffn2_b     = (const float*)d_in[21];
    const float* ln2_g      = (const float*)d_in[22];
    const float* ln2_b      = (const float*)d_in[23];
    const float* pool_w     = (const float*)d_in[24];
    const float* pool_b     = (const float*)d_in[25];
    const float* fc_w       = (const float*)d_in[26];
    const float* fc_b       = (const float*)d_in[27];
    float* out = (float*)d_out;

    float *px, *ptmp, *pctx, *pqkv, *phdn, *pkf, *pvf, *pscores;
    cudaGetSymbolAddress((void**)&px,      g_x);
    cudaGetSymbolAddress((void**)&ptmp,    g_tmp);
    cudaGetSymbolAddress((void**)&pctx,    g_ctx);
    cudaGetSymbolAddress((void**)&pqkv,    g_qkv);
    cudaGetSymbolAddress((void**)&phdn,    g_hdn);
    cudaGetSymbolAddress((void**)&pkf,     g_kf);
    cudaGetSymbolAddress((void**)&pvf,     g_vf);
    cudaGetSymbolAddress((void**)&pscores, g_scores);

    init_kernel<<<1, 1>>>();
    embed_ln_kernel<<<NT, 256>>>(input_ids, word_emb, pos_emb, type_emb, emb_ln_g, emb_ln_b);

    for (int l = 0; l < LL; l++) {
        // ---- prefix MoE ----
        gate_logits_kernel<<<NEXP, 256>>>(expert_emb, gate_w, gate_b, l);
        gate_finalize_kernel<<<1, 32>>>();
        ckcv_kernel<<<(PP * DD + 255) / 256, 256>>>(expert_emb, l);
        proj_cv_kernel<<<(PP * DD + 255) / 256, 256>>>(proj_w, proj_b, l);

        // ---- QKV ----
        gemm(px, qkv_w + (long long)l * DD * QKV_COLS, pqkv,
             NT, QKV_COLS, DD, DD, QKV_COLS, QKV_COLS, false);
        {
            long long total = (long long)NT * QKV_COLS;
            bias_add_kernel<<<(int)((total + 255) / 256), 256>>>(pqkv, qkv_b + (long long)l * QKV_COLS, total, QKV_COLS);
        }

        // ---- assemble kf/vf ----
        {
            long long total = (long long)PB * HH * KV_PAD * EE;
            fill_kfvf_kernel<<<(int)((total + 255) / 256), 256>>>();
        }

        // ---- scores = q @ kf^T (batched over B*H) ----
        gemm(pqkv, pkf, pscores,
             SS, KV_PAD, EE, QKV_COLS, EE, KV_PAD, true,
             PB * HH, HH,
             /*isA h*/ EE, /*osA b*/ (long long)SS * QKV_COLS,
             /*isB*/ (long long)KV_PAD * EE, /*osB*/ (long long)HH * KV_PAD * EE,
             /*isC*/ (long long)SS * KV_PAD, /*osC*/ (long long)HH * SS * KV_PAD);

        attn_softmax_kernel<<<PB * HH * SS, 128>>>(attn_mask);

        // ---- ctx = probs @ vf ----
        gemm(pscores, pvf, pctx,
             SS, EE, KV_PAD, KV_PAD, EE, DD, false,
             PB * HH, HH,
             /*isA*/ (long long)SS * KV_PAD, /*osA*/ (long long)HH * SS * KV_PAD,
             /*isB*/ (long long)KV_PAD * EE, /*osB*/ (long long)HH * KV_PAD * EE,
             /*isC h*/ EE, /*osC b*/ (long long)SS * DD);

        // ---- attn out + residual LN ----
        gemm(pctx, attn_out_w + (long long)l * DD * DD, ptmp,
             NT, DD, DD, DD, DD, DD, false);
        add_ln_kernel<<<NT, 256>>>(px, ptmp, attn_out_b + (long long)l * DD,
                                   ln1_g + (long long)l * DD, ln1_b + (long long)l * DD);

        // ---- FFN ----
        gemm(px, ffn1_w + (long long)l * DD * FFN_COLS, phdn,
             NT, FFN_COLS, DD, DD, FFN_COLS, FFN_COLS, false);
        {
            long long total = (long long)NT * FFN_COLS;
            bias_gelu_kernel<<<(int)((total + 255) / 256), 256>>>(phdn, ffn1_b + (long long)l * FFN_COLS, total, FFN_COLS);
        }
        gemm(phdn, ffn2_w + (long long)l * FFN_COLS * DD, ptmp,
             NT, DD, FFN_COLS, FFN_COLS, DD, DD, false);
        add_ln_kernel<<<NT, 256>>>(px, ptmp, ffn2_b + (long long)l * DD,
                                   ln2_g + (long long)l * DD, ln2_b + (long long)l * DD);
    }

    pool_kernel<<<(PB * DD + 255) / 256, 256>>>(pool_w, pool_b);
    final_kernel<<<1, 128>>>(fc_w, fc_b, out, out_size);
}

// round 3
// speedup vs baseline: 2.0690x; 2.0690x over previous
#include <cuda_runtime.h>
#include <cuda_bf16.h>
#include <mma.h>
#include <math.h>
#include <cstdint>
#include <type_traits>

using namespace nvcuda;

// ---------------- problem constants ----------------
#define PB 32          // batch
#define SS 512         // seq
#define DD 768
#define HH 12
#define EE 64
#define LL 12
#define PP 20          // prefix len
#define NEXP 9
#define NT (PB*SS)     // 16384 tokens
#define KV_RAW (PP+SS)        // 532
#define KV_PAD 576            // padded keys (multiple of 64)
#define QKV_COLS (3*DD)       // 2304
#define FFN_COLS (4*DD)       // 3072

// ---------------- scratch (device globals; no runtime alloc) ----------------
__device__ float g_x   [(long long)NT*DD];
__device__ float g_tmp [(long long)NT*DD];
__device__ float g_ctx [(long long)NT*DD];
__device__ float g_qkv [(long long)NT*QKV_COLS];
__device__ float g_hdn [(long long)NT*FFN_COLS];
__device__ float g_kf  [(long long)PB*HH*KV_PAD*EE];
__device__ float g_vf  [(long long)PB*HH*KV_PAD*EE];
__device__ float g_scores[(long long)PB*HH*SS*KV_PAD];
__device__ float g_ck  [PP*DD];
__device__ float g_cv  [PP*DD];
__device__ float g_cvp [PP*DD];
__device__ float g_gl  [NEXP];
__device__ float g_w   [NEXP];
__device__ float g_moe [1];
__device__ float g_pooled[PB*DD];

// ---------------- reductions ----------------
__device__ __forceinline__ float block_reduce_sum(float v, float* red) {
    int lane = threadIdx.x & 31, wid = threadIdx.x >> 5;
    #pragma unroll
    for (int o = 16; o > 0; o >>= 1) v += __shfl_down_sync(0xffffffffu, v, o);
    if (lane == 0) red[wid] = v;
    __syncthreads();
    int nw = (blockDim.x + 31) >> 5;
    v = (threadIdx.x < nw) ? red[threadIdx.x] : 0.f;
    if (wid == 0) {
        #pragma unroll
        for (int o = 16; o > 0; o >>= 1) v += __shfl_down_sync(0xffffffffu, v, o);
        if (lane == 0) red[0] = v;
    }
    __syncthreads();
    float r = red[0];
    __syncthreads();
    return r;
}

__device__ __forceinline__ float block_reduce_max(float v, float* red) {
    int lane = threadIdx.x & 31, wid = threadIdx.x >> 5;
    #pragma unroll
    for (int o = 16; o > 0; o >>= 1) v = fmaxf(v, __shfl_down_sync(0xffffffffu, v, o));
    if (lane == 0) red[wid] = v;
    __syncthreads();
    int nw = (blockDim.x + 31) >> 5;
    v = (threadIdx.x < nw) ? red[threadIdx.x] : -1e30f;
    if (wid == 0) {
        #pragma unroll
        for (int o = 16; o > 0; o >>= 1) v = fmaxf(v, __shfl_down_sync(0xffffffffu, v, o));
        if (lane == 0) red[0] = v;
    }
    __syncthreads();
    float r = red[0];
    __syncthreads();
    return r;
}

// ---------------- cp.async helpers ----------------
__device__ __forceinline__ void cp_async16(void* smem, const void* gmem) {
    unsigned int s = (unsigned int)__cvta_generic_to_shared(smem);
    asm volatile("cp.async.cg.shared.global [%0], [%1], 16;\n" :: "r"(s), "l"(gmem));
}
__device__ __forceinline__ void cp_commit() {
    asm volatile("cp.async.commit_group;\n" ::: "memory");
}
__device__ __forceinline__ void cp_wait0() {
    asm volatile("cp.async.wait_group 0;\n" ::: "memory");
}

// ---------------- tf32 WMMA GEMM, cp.async double-buffered ----------------
// BK=16. 256 threads = 8 warps laid out WM_ x WN_. Warp tile (BM/WM_)x(BN/WN_).
// BT=true: B is [N][K] row-major -> smem [BN][BK], col_major matrix_b fragments.
template<int BM, int BN, int WM_, int WN_, bool BT>
__global__ void __launch_bounds__(256)
gemm_ta_kernel(const float* __restrict__ A, const float* __restrict__ B,
               float* __restrict__ C,
               int K, int lda, int ldb, int ldc, int inner,
               long long isA, long long osA,
               long long isB, long long osB,
               long long isC, long long osC)
{
    constexpr int BK = 16;
    constexpr int LDA_S = BK + 4;                     // 20
    constexpr int LDB_S = BT ? (BK + 4) : (BN + 4);
    constexpr int BROWS = BT ? BN : BK;
    __shared__ __align__(16) float As[2][BM * LDA_S];
    __shared__ __align__(16) float Bs[2][BROWS * LDB_S];

    int z = blockIdx.z;
    long long zi = z % inner, zo = z / inner;
    const float* Ab = A + zi * isA + zo * osA;
    const float* Bb = B + zi * isB + zo * osB;
    float*       Cb = C + zi * isC + zo * osC;

    const int bm = blockIdx.y * BM;
    const int bn = blockIdx.x * BN;
    const int tid = threadIdx.x;
    const int warp = tid >> 5;
    const int wm = warp % WM_;
    const int wn = warp / WM_;
    constexpr int WTM = BM / WM_;
    constexpr int WTN = BN / WN_;
    constexpr int AM  = WTM / 16;
    constexpr int BNF = WTN / 16;

    using BLayout = typename std::conditional<BT, wmma::col_major, wmma::row_major>::type;

    wmma::fragment<wmma::accumulator, 16, 16, 8, float> acc[AM][BNF];
    #pragma unroll
    for (int i = 0; i < AM; i++)
        #pragma unroll
        for (int j = 0; j < BNF; j++) wmma::fill_fragment(acc[i][j], 0.f);

    auto load_tile = [&](int k0, int buf) {
        constexpr int AV = BM * BK / 4;               // float4 count for A
        #pragma unroll
        for (int i = tid; i < AV; i += 256) {
            int r  = i >> 2;                          // BK/4 == 4
            int c4 = (i & 3) << 2;
            cp_async16(&As[buf][r * LDA_S + c4],
                       Ab + (long long)(bm + r) * lda + k0 + c4);
        }
        if (BT) {
            constexpr int BV = BN * BK / 4;
            #pragma unroll
            for (int i = tid; i < BV; i += 256) {
                int r  = i >> 2;
                int c4 = (i & 3) << 2;
                cp_async16(&Bs[buf][r * LDB_S + c4],
                           Bb + (long long)(bn + r) * ldb + k0 + c4);
            }
        } else {
            constexpr int CPR = BN / 4;               // float4 per B row
            constexpr int BV  = BK * CPR;
            #pragma unroll
            for (int i = tid; i < BV; i += 256) {
                int r  = i / CPR;
                int c4 = (i % CPR) << 2;
                cp_async16(&Bs[buf][r * LDB_S + c4],
                           Bb + (long long)(k0 + r) * ldb + bn + c4);
            }
        }
        cp_commit();
    };

    auto compute = [&](int buf) {
        #pragma unroll
        for (int kk = 0; kk < BK; kk += 8) {
            wmma::fragment<wmma::matrix_a, 16, 16, 8, wmma::precision::tf32, wmma::row_major> af[AM];
            wmma::fragment<wmma::matrix_b, 16, 16, 8, wmma::precision::tf32, BLayout> bf[BNF];
            #pragma unroll
            for (int i = 0; i < AM; i++) {
                wmma::load_matrix_sync(af[i], &As[buf][(wm * WTM + i * 16) * LDA_S + kk], LDA_S);
                #pragma unroll
                for (int t = 0; t < af[i].num_elements; t++)
                    af[i].x[t] = wmma::__float_to_tf32(af[i].x[t]);
            }
            #pragma unroll
            for (int j = 0; j < BNF; j++) {
                if (BT)
                    wmma::load_matrix_sync(bf[j], &Bs[buf][(wn * WTN + j * 16) * LDB_S + kk], LDB_S);
                else
                    wmma::load_matrix_sync(bf[j], &Bs[buf][kk * LDB_S + wn * WTN + j * 16], LDB_S);
                #pragma unroll
                for (int t = 0; t < bf[j].num_elements; t++)
                    bf[j].x[t] = wmma::__float_to_tf32(bf[j].x[t]);
            }
            #pragma unroll
            for (int i = 0; i < AM; i++)
                #pragma unroll
                for (int j = 0; j < BNF; j++)
                    wmma::mma_sync(acc[i][j], af[i], bf[j], acc[i][j]);
        }
    };

    const int nk = K / BK;
    load_tile(0, 0);
    for (int t = 0; t < nk; t++) {
        cp_wait0();
        __syncthreads();
        if (t + 1 < nk) load_tile((t + 1) * BK, (t + 1) & 1);
        compute(t & 1);
        __syncthreads();
    }

    #pragma unroll
    for (int i = 0; i < AM; i++)
        #pragma unroll
        for (int j = 0; j < BNF; j++)
            wmma::store_matrix_sync(
                &Cb[(long long)(bm + wm * WTM + i * 16) * ldc + bn + wn * WTN + j * 16],
                acc[i][j], ldc, wmma::mem_row_major);
}

// large GEMMs: 128x128 tiles
static void gemm_big(const float* A, const float* B, float* C,
                     int M, int N, int K, int lda, int ldb, int ldc)
{
    dim3 g(N / 128, M / 128, 1), blk(256);
    gemm_ta_kernel<128, 128, 2, 4, false><<<g, blk>>>(A, B, C, K, lda, ldb, ldc,
                                                      1, 0, 0, 0, 0, 0, 0);
}

// batched attention GEMMs: 128x64 tiles
template<bool BT>
static void gemm_attn(const float* A, const float* B, float* C,
                      int M, int N, int K, int lda, int ldb, int ldc,
                      int batch, int inner,
                      long long isA, long long osA,
                      long long isB, long long osB,
                      long long isC, long long osC)
{
    dim3 g(N / 64, M / 128, batch), blk(256);
    gemm_ta_kernel<128, 64, 4, 2, BT><<<g, blk>>>(A, B, C, K, lda, ldb, ldc,
                                                  inner, isA, osA, isB, osB, isC, osC);
}

// ---------------- misc kernels ----------------
__global__ void init_kernel() { g_moe[0] = 0.f; }

__global__ void embed_ln_kernel(const int* __restrict__ ids,
                                const float* __restrict__ we,
                                const float* __restrict__ pe,
                                const float* __restrict__ te,
                                const float* __restrict__ g,
                                const float* __restrict__ b)
{
    int t = blockIdx.x;
    int s = t & (SS - 1);
    int id = ids[t];
    __shared__ float buf[DD];
    __shared__ float red[32];
    for (int d = threadIdx.x; d < DD; d += blockDim.x)
        buf[d] = we[(long long)id * DD + d] + pe[(long long)s * DD + d] + te[d];
    __syncthreads();
    float s0 = 0.f;
    for (int d = threadIdx.x; d < DD; d += blockDim.x) s0 += buf[d];
    float mean = block_reduce_sum(s0, red) * (1.f / DD);
    float v0 = 0.f;
    for (int d = threadIdx.x; d < DD; d += blockDim.x) { float df = buf[d] - mean; v0 += df * df; }
    float var = block_reduce_sum(v0, red) * (1.f / DD);
    float inv = rsqrtf(var + 1e-12f);
    for (int d = threadIdx.x; d < DD; d += blockDim.x)
        g_x[(long long)t * DD + d] = (buf[d] - mean) * inv * g[d] + b[d];
}

// x = LN(x + delta + bias)
__global__ void add_ln_kernel(float* __restrict__ x, const float* __restrict__ delta,
                              const float* __restrict__ bias,
                              const float* __restrict__ g, const float* __restrict__ b)
{
    int t = blockIdx.x;
    __shared__ float buf[DD];
    __shared__ float red[32];
    for (int d = threadIdx.x; d < DD; d += blockDim.x)
        buf[d] = x[(long long)t * DD + d] + delta[(long long)t * DD + d] + bias[d];
    __syncthreads();
    float s0 = 0.f;
    for (int d = threadIdx.x; d < DD; d += blockDim.x) s0 += buf[d];
    float mean = block_reduce_sum(s0, red) * (1.f / DD);
    float v0 = 0.f;
    for (int d = threadIdx.x; d < DD; d += blockDim.x) { float df = buf[d] - mean; v0 += df * df; }
    float var = block_reduce_sum(v0, red) * (1.f / DD);
    float inv = rsqrtf(var + 1e-12f);
    for (int d = threadIdx.x; d < DD; d += blockDim.x)
        x[(long long)t * DD + d] = (buf[d] - mean) * inv * g[d] + b[d];
}

__global__ void bias_add4_kernel(float4* __restrict__ buf, const float* __restrict__ bias,
                                 long long total4, int cols4)
{
    long long i = (long long)blockIdx.x * blockDim.x + threadIdx.x;
    if (i >= total4) return;
    int c = (int)(i % cols4) * 4;
    float4 v = buf[i];
    v.x += bias[c]; v.y += bias[c + 1]; v.z += bias[c + 2]; v.w += bias[c + 3];
    buf[i] = v;
}

__device__ __forceinline__ float gelu1(float v) {
    return 0.5f * v * (1.f + erff(v * 0.70710678118654752f));
}

__global__ void bias_gelu4_kernel(float4* __restrict__ buf, const float* __restrict__ bias,
                                  long long total4, int cols4)
{
    long long i = (long long)blockIdx.x * blockDim.x + threadIdx.x;
    if (i >= total4) return;
    int c = (int)(i % cols4) * 4;
    float4 v = buf[i];
    v.x = gelu1(v.x + bias[c]);
    v.y = gelu1(v.y + bias[c + 1]);
    v.z = gelu1(v.z + bias[c + 2]);
    v.w = gelu1(v.w + bias[c + 3]);
    buf[i] = v;
}

// gate logits: one block per expert n
__global__ void gate_logits_kernel(const float* __restrict__ emb,
                                   const float* __restrict__ gw,
                                   const float* __restrict__ gb, int l)
{
    int n = blockIdx.x;
    __shared__ float red[32];
    float acc = 0.f;
    for (int i = threadIdx.x; i < PP * DD; i += blockDim.x) {
        int p = i / DD, rest = i - p * DD;
        long long off = (long long)p * (LL * 2 * DD) + (long long)l * (2 * DD) + rest;
        float gi = 0.f;
        #pragma unroll
        for (int e = 0; e < NEXP; e++)
            gi += emb[(long long)e * PP * LL * 2 * DD + off];
        acc += gi * gw[(long long)l * (PP * DD * NEXP) + (long long)i * NEXP + n];
    }
    acc = block_reduce_sum(acc, red);
    if (threadIdx.x == 0) g_gl[n] = acc + gb[l * NEXP + n];
}

__global__ void gate_finalize_kernel()
{
    if (threadIdx.x == 0) {
        float mx = g_gl[0];
        #pragma unroll
        for (int i = 1; i < NEXP; i++) mx = fmaxf(mx, g_gl[i]);
        float e[NEXP], s = 0.f;
        #pragma unroll
        for (int i = 0; i < NEXP; i++) { e[i] = expf(g_gl[i] - mx); s += e[i]; }
        float inv = 1.f / s, m2 = 0.f;
        #pragma unroll
        for (int i = 0; i < NEXP; i++) { float wi = e[i] * inv; g_w[i] = wi; m2 += wi * wi; }
        g_moe[0] += m2;
    }
}

__global__ void ckcv_kernel(const float* __restrict__ emb, int l)
{
    int i = blockIdx.x * blockDim.x + threadIdx.x;
    if (i >= PP * DD) return;
    int p = i / DD, rest = i - p * DD;
    long long off = (long long)p * (LL * 2 * DD) + (long long)l * (2 * DD) + rest;
    float sk = 0.f, sv = 0.f;
    #pragma unroll
    for (int e = 0; e < NEXP; e++) {
        long long eb = (long long)e * PP * LL * 2 * DD;
        float w = g_w[e];
        sk += w * emb[eb + off];
        sv += w * emb[eb + off + DD];
    }
    g_ck[i] = sk;
    g_cv[i] = sv;
}

__global__ void proj_cv_kernel(const float* __restrict__ pw, const float* __restrict__ pb, int l)
{
    int i = blockIdx.x * blockDim.x + threadIdx.x;
    if (i >= PP * DD) return;
    int p = i / DD, j = i - p * DD;
    const float* W = pw + (long long)l * DD * DD;
    float s = pb[l * DD + j];
    const float* cvr = g_cv + p * DD;
    for (int d = 0; d < DD; d++) s += cvr[d] * W[(long long)d * DD + j];
    g_cvp[i] = s;
}

__global__ void fill_kfvf_kernel()
{
    long long idx = (long long)blockIdx.x * blockDim.x + threadIdx.x;
    const long long total = (long long)PB * HH * KV_PAD * EE;
    if (idx >= total) return;
    int c = (int)(idx & (EE - 1));
    long long r = idx >> 6;
    int row = (int)(r % KV_PAD);
    long long bh = r / KV_PAD;
    int h = (int)(bh % HH);
    int b = (int)(bh / HH);
    float kvv, vvv;
    if (row < PP) {
        kvv = g_ck[row * DD + h * EE + c];
        vvv = g_cvp[row * DD + h * EE + c];
    } else if (row < KV_RAW) {
        int s = row - PP;
        long long base = ((long long)(b * SS + s)) * QKV_COLS + h * EE + c;
        kvv = g_qkv[base + DD];
        vvv = g_qkv[base + 2 * DD];
    } else {
        kvv = 0.f; vvv = 0.f;
    }
    g_kf[idx] = kvv;
    g_vf[idx] = vvv;
}

__global__ void attn_softmax_kernel(const float* __restrict__ amask)
{
    long long row = blockIdx.x;                 // over B*H*S
    int b = (int)(row / (HH * SS));
    float* srow = g_scores + row * KV_PAD;
    const float scale = 0.125f;                 // 1/sqrt(64)
    __shared__ float red[32];
    int tid = threadIdx.x;

    float mx = -1e30f;
    for (int j = tid; j < KV_RAW; j += blockDim.x) {
        float bias = 0.f;
        if (j >= PP) bias = (1.0f - amask[(long long)b * SS + (j - PP)]) * -10000.0f;
        float v = srow[j] * scale + bias;
        srow[j] = v;
        mx = fmaxf(mx, v);
    }
    mx = block_reduce_max(mx, red);
    float sum = 0.f;
    for (int j = tid; j < KV_RAW; j += blockDim.x) {
        float e = __expf(srow[j] - mx);
        srow[j] = e;
        sum += e;
    }
    sum = block_reduce_sum(sum, red);
    float inv = 1.f / sum;
    for (int j = tid; j < KV_RAW; j += blockDim.x) srow[j] *= inv;
    for (int j = KV_RAW + tid; j < KV_PAD; j += blockDim.x) srow[j] = 0.f;
}

__global__ void pool_kernel(const float* __restrict__ pw, const float* __restrict__ pb)
{
    int i = blockIdx.x * blockDim.x + threadIdx.x;
    if (i >= PB * DD) return;
    int b = i / DD, j = i - b * DD;
    float s = pb[j];
    const float* xr = g_x + (long long)b * SS * DD;   // token 0 of batch b
    for (int d = 0; d < DD; d++) s += xr[d] * pw[(long long)d * DD + j];
    g_pooled[i] = tanhf(s);
}

__global__ void final_kernel(const float* __restrict__ fw, const float* __restrict__ fb,
                             float* __restrict__ out, int out_size)
{
    int i = blockIdx.x * blockDim.x + threadIdx.x;
    if (i < PB * 2) {
        int b = i >> 1, c = i & 1;
        float s = fb[c];
        const float* pr = g_pooled + b * DD;
        for (int j = 0; j < DD; j++) s += pr[j] * fw[j * 2 + c];
        out[i] = s;
    }
    if (i == PB * 2 && out_size > PB * 2) out[PB * 2] = g_moe[0] / (float)LL;
}

// ---------------- launch ----------------
extern "C" void kernel_launch(void* const* d_in, const int* in_sizes, int n_in,
                              void* d_out, int out_size)
{
    const int*   input_ids  = (const int*)  d_in[0];
    const float* attn_mask  = (const float*)d_in[1];
    const float* expert_emb = (const float*)d_in[2];
    const float* gate_w     = (const float*)d_in[3];
    const float* gate_b     = (const float*)d_in[4];
    const float* proj_w     = (const float*)d_in[5];
    const float* proj_b     = (const float*)d_in[6];
    const float* word_emb   = (const float*)d_in[7];
    const float* pos_emb    = (const float*)d_in[8];
    const float* type_emb   = (const float*)d_in[9];
    const float* emb_ln_g   = (const float*)d_in[10];
    const float* emb_ln_b   = (const float*)d_in[11];
    const float* qkv_w      = (const float*)d_in[12];
    const float* qkv_b      = (const float*)d_in[13];
    const float* attn_out_w = (const float*)d_in[14];
    const float* attn_out_b = (const float*)d_in[15];
    const float* ln1_g      = (const float*)d_in[16];
    const float* ln1_b      = (const float*)d_in[17];
    const float* ffn1_w     = (const float*)d_in[18];
    const float* ffn1_b     = (const float*)d_in[19];
    const float* ffn2_w     = (const float*)d_in[20];
    const float* ffn2_b     = (const float*)d_in[21];
    const float* ln2_g      = (const float*)d_in[22];
    const float* ln2_b      = (const float*)d_in[23];
    const float* pool_w     = (const float*)d_in[24];
    const float* pool_b     = (const float*)d_in[25];
    const float* fc_w       = (const float*)d_in[26];
    const float* fc_b       = (const float*)d_in[27];
    float* out = (float*)d_out;

    float *px, *ptmp, *pctx, *pqkv, *phdn, *pkf, *pvf, *pscores;
    cudaGetSymbolAddress((void**)&px,      g_x);
    cudaGetSymbolAddress((void**)&ptmp,    g_tmp);
    cudaGetSymbolAddress((void**)&pctx,    g_ctx);
    cudaGetSymbolAddress((void**)&pqkv,    g_qkv);
    cudaGetSymbolAddress((void**)&phdn,    g_hdn);
    cudaGetSymbolAddress((void**)&pkf,     g_kf);
    cudaGetSymbolAddress((void**)&pvf,     g_vf);
    cudaGetSymbolAddress((void**)&pscores, g_scores);

    init_kernel<<<1, 1>>>();
    embed_ln_kernel<<<NT, 256>>>(input_ids, word_emb, pos_emb, type_emb, emb_ln_g, emb_ln_b);

    for (int l = 0; l < LL; l++) {
        // ---- prefix MoE ----
        gate_logits_kernel<<<NEXP, 256>>>(expert_emb, gate_w, gate_b, l);
        gate_finalize_kernel<<<1, 32>>>();
        ckcv_kernel<<<(PP * DD + 255) / 256, 256>>>(expert_emb, l);
        proj_cv_kernel<<<(PP * DD + 255) / 256, 256>>>(proj_w, proj_b, l);

        // ---- QKV ----
        gemm_big(px, qkv_w + (long long)l * DD * QKV_COLS, pqkv,
                 NT, QKV_COLS, DD, DD, QKV_COLS, QKV_COLS);
        {
            long long total4 = (long long)NT * QKV_COLS / 4;
            bias_add4_kernel<<<(int)((total4 + 255) / 256), 256>>>(
                (float4*)pqkv, qkv_b + (long long)l * QKV_COLS, total4, QKV_COLS / 4);
        }

        // ---- assemble kf/vf ----
        {
            long long total = (long long)PB * HH * KV_PAD * EE;
            fill_kfvf_kernel<<<(int)((total + 255) / 256), 256>>>();
        }

        // ---- scores = q @ kf^T (batched over B*H) ----
        gemm_attn<true>(pqkv, pkf, pscores,
                        SS, KV_PAD, EE, QKV_COLS, EE, KV_PAD,
                        PB * HH, HH,
                        /*isA h*/ EE, /*osA b*/ (long long)SS * QKV_COLS,
                        /*isB*/ (long long)KV_PAD * EE, /*osB*/ (long long)HH * KV_PAD * EE,
                        /*isC*/ (long long)SS * KV_PAD, /*osC*/ (long long)HH * SS * KV_PAD);

        attn_softmax_kernel<<<PB * HH * SS, 128>>>(attn_mask);

        // ---- ctx = probs @ vf ----
        gemm_attn<false>(pscores, pvf, pctx,
                         SS, EE, KV_PAD, KV_PAD, EE, DD,
                         PB * HH, HH,
                         /*isA*/ (long long)SS * KV_PAD, /*osA*/ (long long)HH * SS * KV_PAD,
                         /*isB*/ (long long)KV_PAD * EE, /*osB*/ (long long)HH * KV_PAD * EE,
                         /*isC h*/ EE, /*osC b*/ (long long)SS * DD);

        // ---- attn out + residual LN ----
        gemm_big(pctx, attn_out_w + (long long)l * DD * DD, ptmp,
                 NT, DD, DD, DD, DD, DD);
        add_ln_kernel<<<NT, 256>>>(px, ptmp, attn_out_b + (long long)l * DD,
                                   ln1_g + (long long)l * DD, ln1_b + (long long)l * DD);

        // ---- FFN ----
        gemm_big(px, ffn1_w + (long long)l * DD * FFN_COLS, phdn,
                 NT, FFN_COLS, DD, DD, FFN_COLS, FFN_COLS);
        {
            long long total4 = (long long)NT * FFN_COLS / 4;
            bias_gelu4_kernel<<<(int)((total4 + 255) / 256), 256>>>(
                (float4*)phdn, ffn1_b + (long long)l * FFN_COLS, total4, FFN_COLS / 4);
        }
        gemm_big(phdn, ffn2_w + (long long)l * FFN_COLS * DD, ptmp,
                 NT, DD, FFN_COLS, FFN_COLS, DD, DD);
        add_ln_kernel<<<NT, 256>>>(px, ptmp, ffn2_b + (long long)l * DD,
                                   ln2_g + (long long)l * DD, ln2_b + (long long)l * DD);
    }

    pool_kernel<<<(PB * DD + 255) / 256, 256>>>(pool_w, pool_b);
    final_kernel<<<1, 128>>>(fc_w, fc_b, out, out_size);
}